// round 14
// baseline (speedup 1.0000x reference)
#include <cuda_runtime.h>
#include <cuda_fp16.h>
#include <math.h>
#include <stdint.h>

// Problem constants
#define E_DIM   256
#define NA      900
#define BS      2
#define NCAM    6
#define NLVL    4
#define NPTS    13
#define NG      8
#define NANCH   (BS*NA)          // 1800
#define WO      416              // G*NL*NPTS
#define NSAMP   (NCAM*NLVL*NPTS) // 312
#define SOFTN   312
#define MTOT    (NANCH+12)       // 1812 rows in combined GEMM

// Levels: 0: 64x176  1: 32x88  2: 16x44  3: 8x22
#define FMT_TOTAL 45957120

__device__ __half g_fmt[FMT_TOTAL];
__device__ float  g_featW[MTOT*WO];   // rows 0..1799: featW; rows 1800..1811: ceW (no bias)
__device__ float  g_h1[12*E_DIM];
__device__ float  g_ce2[12*E_DIM];
__device__ float  g_ce[12*E_DIM];
__device__ float  g_ls[NANCH*18];
__device__ float  g_fused[NANCH*E_DIM];

__constant__ float c_fix[7][3] = {
  {0.f,0.f,0.f},{0.45f,0.f,0.f},{-0.45f,0.f,0.f},{0.f,0.45f,0.f},
  {0.f,-0.45f,0.f},{0.f,0.f,0.45f},{0.f,0.f,-0.45f}};

__constant__ int c_lW[4]   = {176,88,44,22};
__constant__ int c_lH[4]   = {64,32,16,8};
__constant__ int c_lOff[4] = {0,34603008,43253760,45416448};
__constant__ int c_lStr[4] = {2883584,720896,180224,45056};   // HW*256 per image

// ---------- merged vectorized transpose+convert (all 12 images) ----------
__global__ __launch_bounds__(256) void transpose_all_kernel(
    const float* __restrict__ f0, const float* __restrict__ f1,
    const float* __restrict__ f2, const float* __restrict__ f3){
  int bid = blockIdx.x;
  int l, bl;
  if(bid < 8448){ l=0; bl=bid; }
  else if(bid < 10560){ l=1; bl=bid-8448; }
  else if(bid < 11088){ l=2; bl=bid-10560; }
  else { l=3; bl=bid-11088; }
  const float* src; int HW, thw; int dstOff;
  if(l==0){src=f0;HW=11264;thw=176;dstOff=0;}
  else if(l==1){src=f1;HW=2816;thw=44;dstOff=34603008;}
  else if(l==2){src=f2;HW=704;thw=11;dstOff=43253760;}
  else {src=f3;HW=176;thw=3;dstOff=45416448;}
  int e_t = bl & 3; int tmp = bl >> 2;
  int hw_t = tmp % thw; int img = tmp / thw;
  int e0 = e_t*64, hw0 = hw_t*64;
  const float* s = src + (size_t)img*E_DIM*HW;
  __half* d = g_fmt + dstOff + (size_t)img*HW*E_DIM;

  __shared__ float sm[64][65];
  int t = threadIdx.x;
  int col = t & 15, row0 = t >> 4;
  int hwc = hw0 + col*4;
  if(hwc < HW){
    #pragma unroll
    for(int i=0;i<4;i++){
      int r = row0 + 16*i;
      float4 v = __ldcs((const float4*)(s + (size_t)(e0+r)*HW + hwc));
      sm[r][col*4+0]=v.x; sm[r][col*4+1]=v.y; sm[r][col*4+2]=v.z; sm[r][col*4+3]=v.w;
    }
  }
  __syncthreads();
  int chunk = t & 7, hrow = t >> 3;
  #pragma unroll
  for(int i=0;i<2;i++){
    int hw = hrow + 32*i;
    if(hw0+hw < HW){
      __half2 h[4];
      #pragma unroll
      for(int j=0;j<4;j++)
        h[j] = __floats2half2_rn(sm[8*chunk+2*j][hw], sm[8*chunk+2*j+1][hw]);
      *(uint4*)(d + (size_t)(hw0+hw)*E_DIM + e0 + 8*chunk) = *(uint4*)h;
    }
  }
}

// ---------- tiled fp32 GEMM; rows<M1 use A(+A2), rows>=M1 use A3 ----------
__global__ __launch_bounds__(256) void gemm_kernel(
    const float* __restrict__ A, const float* __restrict__ A2,
    const float* __restrict__ A3, int M1,
    const float* __restrict__ B, const float* __restrict__ bias,
    float* __restrict__ C, int M, int N, int ldc){
  __shared__ float As[16][64];
  __shared__ float Bs[16][68];
  int m0 = blockIdx.x*64, n0 = blockIdx.y*64;
  int t = threadIdx.x;
  int tm = t>>4, tn = t&15;
  int rowA = t>>2, kvA = (t&3)<<2;
  int kkB = t>>4, nvB = (t&15)<<2;
  int gm = m0+rowA;
  int gn = n0+nvB;
  float acc[4][4];
  #pragma unroll
  for(int i=0;i<4;i++)
    #pragma unroll
    for(int j=0;j<4;j++) acc[i][j]=0.f;

  const float* Ap = nullptr;
  const float* A2p = nullptr;
  if(gm < M){
    if(A3 && gm >= M1){ Ap = A3 + (size_t)(gm-M1)*E_DIM + kvA; }
    else { Ap = A + (size_t)gm*E_DIM + kvA; if(A2) A2p = A2 + (size_t)gm*E_DIM + kvA; }
  }

  float4 av = make_float4(0,0,0,0), bv = make_float4(0,0,0,0);
  if(Ap){
    av = *(const float4*)(Ap);
    if(A2p){ float4 a2 = *(const float4*)(A2p); av.x+=a2.x; av.y+=a2.y; av.z+=a2.z; av.w+=a2.w; }
  }
  {
    const float* bp = B + (size_t)kkB*N + gn;
    if(gn+3 < N) bv = *(const float4*)bp;
    else { if(gn<N) bv.x=bp[0]; if(gn+1<N) bv.y=bp[1]; if(gn+2<N) bv.z=bp[2]; }
  }

  for(int k0=0; k0<E_DIM; k0+=16){
    __syncthreads();
    As[kvA+0][rowA]=av.x; As[kvA+1][rowA]=av.y;
    As[kvA+2][rowA]=av.z; As[kvA+3][rowA]=av.w;
    *(float4*)&Bs[kkB][nvB] = bv;
    __syncthreads();
    if(k0+16 < E_DIM){
      av = make_float4(0,0,0,0);
      if(Ap){
        av = *(const float4*)(Ap + k0 + 16);
        if(A2p){ float4 a2 = *(const float4*)(A2p + k0 + 16); av.x+=a2.x; av.y+=a2.y; av.z+=a2.z; av.w+=a2.w; }
      }
      const float* bp = B + (size_t)(k0+16+kkB)*N + gn;
      if(gn+3 < N) bv = *(const float4*)bp;
      else { bv=make_float4(0,0,0,0); if(gn<N) bv.x=bp[0]; if(gn+1<N) bv.y=bp[1]; if(gn+2<N) bv.z=bp[2]; }
    }
    #pragma unroll
    for(int kk=0;kk<16;kk++){
      float a[4], b[4];
      *(float4*)a = *(const float4*)&As[kk][tm*4];
      *(float4*)b = *(const float4*)&Bs[kk][tn*4];
      #pragma unroll
      for(int i=0;i<4;i++)
        #pragma unroll
        for(int j=0;j<4;j++)
          acc[i][j] += a[i]*b[j];
    }
  }
  #pragma unroll
  for(int i=0;i<4;i++){
    int gmo = m0 + tm*4 + i;
    if(gmo >= M) continue;
    int gn0 = n0 + tn*4;
    float* cp = C + (size_t)gmo*ldc + gn0;
    #pragma unroll
    for(int j=0;j<4;j++){
      int gno = gn0 + j;
      if(gno < N) cp[j] = acc[i][j] + (bias ? bias[gno] : 0.f);
    }
  }
}

// ---------- learned scales ----------
__global__ __launch_bounds__(256) void ls_kernel(const float* __restrict__ iff,
    const float* __restrict__ lfcw, const float* __restrict__ lfcb){
  int idx = blockIdx.x*256 + threadIdx.x;
  if(idx >= NANCH*18) return;
  int a = idx/18, o = idx - 18*a;
  const float* f = iff + (size_t)a*E_DIM;
  float v = lfcb[o];
  #pragma unroll 4
  for(int e=0;e<E_DIM;e++) v += f[e]*lfcw[e*18+o];
  g_ls[idx] = 1.f/(1.f+__expf(-v)) - 0.5f;
}

// ---------- cam layer1: 12->256 + ReLU + LN ----------
__device__ __forceinline__ float blockSum256(float v, float* red){
  int tid = threadIdx.x;
  red[tid] = v; __syncthreads();
  #pragma unroll
  for(int s=128;s>0;s>>=1){
    if(tid<s) red[tid]+=red[tid+s];
    __syncthreads();
  }
  float r = red[0]; __syncthreads();
  return r;
}

__global__ void cam1_kernel(const float* __restrict__ pm,
    const float* __restrict__ ce1w, const float* __restrict__ ce1b,
    const float* __restrict__ ln1g, const float* __restrict__ ln1b){
  int img = blockIdx.x;
  int tid = threadIdx.x;
  __shared__ float cam[12];
  __shared__ float red[E_DIM];
  if(tid<12) cam[tid] = pm[img*16 + tid];
  __syncthreads();
  float v = ce1b[tid];
  #pragma unroll
  for(int i=0;i<12;i++) v += cam[i]*ce1w[i*E_DIM+tid];
  v = fmaxf(v,0.f);
  float m = blockSum256(v, red) * (1.f/E_DIM);
  float dvar = v - m;
  float var = blockSum256(dvar*dvar, red) * (1.f/E_DIM);
  g_h1[img*E_DIM + tid] = dvar * rsqrtf(var + 1e-5f) * ln1g[tid] + ln1b[tid];
}

// ---------- cam layer2 matmul: grid (12,4); 64 outputs x 4 K-slices ----------
__global__ __launch_bounds__(256) void cam2_kernel(
    const float* __restrict__ ce2w, const float* __restrict__ ce2b){
  int img = blockIdx.x, chunk = blockIdx.y;
  int tid = threadIdx.x;
  int ol = tid & 63, ks = tid >> 6;       // output-local 0..63, k-slice 0..3
  int o = chunk*64 + ol;
  __shared__ float h[E_DIM];
  __shared__ float red[4][64];
  h[tid] = g_h1[img*E_DIM + tid];
  __syncthreads();
  float acc = 0.f;
  int k0 = ks*64;
  #pragma unroll 8
  for(int k=0;k<64;k++)
    acc += h[k0+k]*ce2w[(size_t)(k0+k)*E_DIM + o];
  red[ks][ol] = acc;
  __syncthreads();
  if(ks==0)
    g_ce2[img*E_DIM + o] = red[0][ol]+red[1][ol]+red[2][ol]+red[3][ol] + ce2b[o];
}

// ---------- cam layer2 epilogue: ReLU + LN ----------
__global__ void cam_ln_kernel(const float* __restrict__ ln2g, const float* __restrict__ ln2b){
  int img = blockIdx.x;
  int tid = threadIdx.x;
  __shared__ float red[E_DIM];
  float v = fmaxf(g_ce2[img*E_DIM + tid], 0.f);
  float m = blockSum256(v, red) * (1.f/E_DIM);
  float d = v - m;
  float var = blockSum256(d*d, red) * (1.f/E_DIM);
  g_ce[img*E_DIM + tid] = d * rsqrtf(var + 1e-5f) * ln2g[tid] + ln2b[tid];
}

// ---------- main: 512 threads; atomic-free conflict-free reduction ----------
__global__ __launch_bounds__(512) void dfa_main_kernel(
    const float* __restrict__ iff, const float* __restrict__ anc,
    const float* __restrict__ pm, const float* __restrict__ wh,
    const float* __restrict__ wfb,
    float* __restrict__ out){
  int n = blockIdx.x;
  int b = n / NA;
  int tid = threadIdx.x;
  int wid = tid>>5, ln = tid&31;

  __shared__ float sA[11];
  __shared__ float sLS[18];
  __shared__ float sKP[NPTS][3];
  __shared__ float sWgt[NCAM*WO];
  __shared__ float sGX[NSAMP], sGY[NSAMP];
  __shared__ int   sOff[NSAMP];
  __shared__ int   sWHs[NSAMP];
  __shared__ short sSid[NSAMP];
  __shared__ int   sNV;
  __shared__ float sPart[16][E_DIM];   // per-warp partials, layout [w][j*32+ln]

  // phase A: loads + logits + keypoints
  if(tid < E_DIM)
    out[(size_t)n*512 + 256 + tid] = iff[(size_t)n*E_DIM + tid];
  if(tid==0) sNV = 0;
  if(tid<11) sA[tid] = anc[(size_t)n*11+tid];
  if(tid<18) sLS[tid] = g_ls[n*18+tid];
  // vectorized logit assembly: 2496 floats = 624 float4
  {
    const float4* fA = (const float4*)(g_featW + (size_t)n*WO);
    for(int idx4=tid; idx4<624; idx4+=512){
      int c = idx4/104, o4 = idx4 - c*104;
      float4 a = fA[o4];
      float4 ce = *((const float4*)(g_featW + (size_t)(NANCH + b*NCAM+c)*WO) + o4);
      float4 bb = *((const float4*)wfb + o4);
      float4 r;
      r.x = a.x+ce.x+bb.x; r.y = a.y+ce.y+bb.y;
      r.z = a.z+ce.z+bb.z; r.w = a.w+ce.w+bb.w;
      *(float4*)&sWgt[c*WO + o4*4] = r;
    }
  }
  __syncthreads();
  if(tid<NPTS){
    float sx = expf(sA[3]), sy2 = expf(sA[4]), sz = expf(sA[5]);
    float kx,ky,kz;
    if(tid<7){ kx=c_fix[tid][0]*sx; ky=c_fix[tid][1]*sy2; kz=c_fix[tid][2]*sz; }
    else { int i=tid-7; kx=sLS[i*3+0]*sx; ky=sLS[i*3+1]*sy2; kz=sLS[i*3+2]*sz; }
    float sn = sA[6], cs = sA[7];
    sKP[tid][0] = cs*kx - sn*ky + sA[0];
    sKP[tid][1] = sn*kx + cs*ky + sA[1];
    sKP[tid][2] = kz + sA[2];
  }
  __syncthreads();

  // phase B: warps 0-7 softmax (group = wid); warps 8-15 projection + compaction
  if(wid < 8){
    int g = wid;
    float mx = -1e30f;
    for(int j=ln;j<SOFTN;j+=32){
      int c=j/52, k=j-c*52;
      mx = fmaxf(mx, sWgt[c*WO + k*8 + g]);
    }
    #pragma unroll
    for(int o=16;o;o>>=1) mx = fmaxf(mx, __shfl_xor_sync(0xffffffffu, mx, o));
    float sum = 0.f;
    for(int j=ln;j<SOFTN;j+=32){
      int c=j/52, k=j-c*52;
      sum += __expf(sWgt[c*WO + k*8 + g] - mx);
    }
    #pragma unroll
    for(int o=16;o;o>>=1) sum += __shfl_xor_sync(0xffffffffu, sum, o);
    float inv = 1.f/sum;
    for(int j=ln;j<SOFTN;j+=32){
      int c=j/52, k=j-c*52;
      int idx = c*WO + k*8 + g;
      sWgt[idx] = __expf(sWgt[idx] - mx) * inv;
    }
  } else {
    for(int idx=(wid-8)*32+ln; idx<NSAMP; idx+=256){
      int c = idx/52, r = idx - c*52, l = r/13, p = r - l*13;
      const float* P = pm + (size_t)(b*NCAM+c)*16;
      float X = sKP[p][0], Y = sKP[p][1], Z = sKP[p][2];
      float r0 = P[0]*X + P[1]*Y + P[2]*Z  + P[3];
      float r1 = P[4]*X + P[5]*Y + P[6]*Z  + P[7];
      float r2 = P[8]*X + P[9]*Y + P[10]*Z + P[11];
      float z = fmaxf(r2, 1e-5f);
      float iwx = wh[(b*NCAM+c)*2+0], iwy = wh[(b*NCAM+c)*2+1];
      int Wl = c_lW[l], Hl = c_lH[l];
      float fW = (float)Wl, fH = (float)Hl;
      float gx = (r0/z)/iwx*fW - 0.5f;
      float gy = (r1/z)/iwy*fH - 0.5f;
      sGX[idx] = gx; sGY[idx] = gy;
      sOff[idx] = c_lOff[l] + (b*NCAM+c)*c_lStr[l];
      sWHs[idx] = Wl | (Hl<<16);
      if(gx > -1.f && gx < fW && gy > -1.f && gy < fH){
        int pos = atomicAdd(&sNV, 1);
        sSid[pos] = (short)idx;
      }
    }
  }
  __syncthreads();

  // phase C: sampling with 16 warps; lane owns channels [8*ln..8*ln+7] (group ln>>2)
  float acc[8];
  #pragma unroll
  for(int j=0;j<8;j++) acc[j]=0.f;
  int g = ln>>2;
  int nv = sNV;

  for(int i = wid; i < nv; i += 16){
    int s = sSid[i];
    int whp = sWHs[s];
    int Wl = whp & 0xffff, Hl = whp >> 16;
    float gx = sGX[s], gy = sGY[s];
    float x0f = floorf(gx), y0f = floorf(gy);
    float wx1 = gx - x0f, wy1 = gy - y0f;
    float wx0 = 1.f - wx1, wy0 = 1.f - wy1;
    int x0 = (int)x0f, y0 = (int)y0f;
    bool vx0 = (x0 >= 0), vx1 = (x0+1 < Wl);
    bool vy0 = (y0 >= 0), vy1 = (y0+1 < Hl);
    const __half* imgb = g_fmt + sOff[s];
    float sv[8];
    #pragma unroll
    for(int j=0;j<8;j++) sv[j]=0.f;
    #define TAP(px, py, wt) { \
      uint4 u = *((const uint4*)(imgb + ((size_t)((py)*Wl + (px))<<8)) + ln); \
      const __half2* hp = (const __half2*)&u; \
      _Pragma("unroll") \
      for(int j=0;j<4;j++){ \
        float2 f = __half22float2(hp[j]); \
        sv[2*j]   += (wt)*f.x; \
        sv[2*j+1] += (wt)*f.y; \
      } }
    if(vy0){
      if(vx0) TAP(x0,   y0, wx0*wy0);
      if(vx1) TAP(x0+1, y0, wx1*wy0);
    }
    if(vy1){
      if(vx0) TAP(x0,   y0+1, wx0*wy1);
      if(vx1) TAP(x0+1, y0+1, wx1*wy1);
    }
    #undef TAP
    float wt = sWgt[s*8 + g];
    #pragma unroll
    for(int j=0;j<8;j++) acc[j] += wt*sv[j];
  }
  // conflict-free partial stores: position j*32+ln holds channel 8*ln+j
  #pragma unroll
  for(int j=0;j<8;j++) sPart[wid][j*32+ln] = acc[j];
  __syncthreads();
  if(tid < E_DIM){
    // channel ch=tid lives at position (ch&7)*32 + (ch>>3)
    int pos = (tid&7)*32 + (tid>>3);
    float s = 0.f;
    #pragma unroll
    for(int w=0;w<16;w++) s += sPart[w][pos];
    g_fused[(size_t)n*E_DIM + tid] = s;
  }
}

// ---------- host launcher ----------
extern "C" void kernel_launch(void* const* d_in, const int* in_sizes, int n_in,
                              void* d_out, int out_size) {
  int iIF=0, iAE=2, iPM, iWH, iFM0, iFM1, iFM2, iFM3;
  int iANC=1;
  if(in_sizes[3]==192){ iPM=3; iWH=4; iFM0=5; iFM1=6; iFM2=7; iFM3=8; }
  else                { iFM0=3; iFM1=4; iFM2=5; iFM3=6; iPM=7; iWH=8; }
  int iLFW=9, iLFB=10, iC1W=11, iC1B=12, iL1G=13, iL1B=14,
      iC2W=15, iC2B=16, iL2G=17, iL2B=18, iWFW=19, iWFB=20, iOPW=21, iOPB=22;

  const float* iff  = (const float*)d_in[iIF];
  const float* anc  = (const float*)d_in[iANC];
  const float* ae   = (const float*)d_in[iAE];
  const float* pm   = (const float*)d_in[iPM];
  const float* wh   = (const float*)d_in[iWH];
  const float* fm0  = (const float*)d_in[iFM0];
  const float* fm1  = (const float*)d_in[iFM1];
  const float* fm2  = (const float*)d_in[iFM2];
  const float* fm3  = (const float*)d_in[iFM3];
  const float* lfcw = (const float*)d_in[iLFW];
  const float* lfcb = (const float*)d_in[iLFB];
  const float* c1w  = (const float*)d_in[iC1W];
  const float* c1b  = (const float*)d_in[iC1B];
  const float* l1g  = (const float*)d_in[iL1G];
  const float* l1b  = (const float*)d_in[iL1B];
  const float* c2w  = (const float*)d_in[iC2W];
  const float* c2b  = (const float*)d_in[iC2B];
  const float* l2g  = (const float*)d_in[iL2G];
  const float* l2b  = (const float*)d_in[iL2B];
  const float* wfw  = (const float*)d_in[iWFW];
  const float* wfb  = (const float*)d_in[iWFB];
  const float* opw  = (const float*)d_in[iOPW];
  const float* opb  = (const float*)d_in[iOPB];
  float* out = (float*)d_out;

  float* p_featW; cudaGetSymbolAddress((void**)&p_featW, g_featW);
  float* p_fused; cudaGetSymbolAddress((void**)&p_fused, g_fused);
  float* p_ce;    cudaGetSymbolAddress((void**)&p_ce,    g_ce);

  static cudaStream_t s2 = nullptr;
  static cudaEvent_t evFork=nullptr, evJoin=nullptr;
  if(s2 == nullptr){
    cudaStreamCreateWithFlags(&s2, cudaStreamNonBlocking);
    cudaEventCreateWithFlags(&evFork, cudaEventDisableTiming);
    cudaEventCreateWithFlags(&evJoin, cudaEventDisableTiming);
  }

  // fork
  cudaEventRecord(evFork, 0);
  cudaStreamWaitEvent(s2, evFork, 0);

  // stream 0: single merged transpose (full chip)
  transpose_all_kernel<<<11232, 256>>>(fm0, fm1, fm2, fm3);

  // stream 2: weight-side pipeline (independent of g_fmt)
  ls_kernel<<<(NANCH*18 + 255)/256, 256, 0, s2>>>(iff, lfcw, lfcb);
  cam1_kernel<<<12, 256, 0, s2>>>(pm, c1w, c1b, l1g, l1b);
  cam2_kernel<<<dim3(12,4), 256, 0, s2>>>(c2w, c2b);
  cam_ln_kernel<<<12, 256, 0, s2>>>(l2g, l2b);
  // combined GEMM: rows 0..1799 = (iff+ae)@wfw ; rows 1800..1811 = ce@wfw (no bias)
  gemm_kernel<<<dim3(29,7), 256, 0, s2>>>(iff, ae, p_ce, NANCH, wfw, nullptr,
                                          p_featW, MTOT, WO, WO);

  // join
  cudaEventRecord(evJoin, s2);
  cudaStreamWaitEvent(0, evJoin, 0);

  dfa_main_kernel<<<NANCH, 512>>>(iff, anc, pm, wh, wfb, out);
  gemm_kernel<<<dim3(29,4), 256>>>(p_fused, nullptr, nullptr, NANCH, opw, opb,
                                   out, NANCH, E_DIM, 512);
}

// round 15
// speedup vs baseline: 1.0018x; 1.0018x over previous
#include <cuda_runtime.h>
#include <cuda_fp16.h>
#include <math.h>
#include <stdint.h>

// Problem constants
#define E_DIM   256
#define NA      900
#define BS      2
#define NCAM    6
#define NLVL    4
#define NPTS    13
#define NG      8
#define NANCH   (BS*NA)          // 1800
#define WO      416              // G*NL*NPTS
#define NSAMP   (NCAM*NLVL*NPTS) // 312
#define SOFTN   312
#define MTOT    (NANCH+12)       // 1812 rows in combined GEMM

// Levels: 0: 64x176  1: 32x88  2: 16x44  3: 8x22
#define FMT_TOTAL 45957120

__device__ __half g_fmt[FMT_TOTAL];
__device__ float  g_featW[MTOT*WO];   // rows 0..1799: featW; rows 1800..1811: ceW (no bias)
__device__ float  g_h1[12*E_DIM];
__device__ float  g_ce2[12*E_DIM];
__device__ float  g_ce[12*E_DIM];
__device__ float  g_ls[NANCH*18];
__device__ float  g_fused[NANCH*E_DIM];

__constant__ float c_fix[7][3] = {
  {0.f,0.f,0.f},{0.45f,0.f,0.f},{-0.45f,0.f,0.f},{0.f,0.45f,0.f},
  {0.f,-0.45f,0.f},{0.f,0.f,0.45f},{0.f,0.f,-0.45f}};

__constant__ int c_lW[4]   = {176,88,44,22};
__constant__ int c_lH[4]   = {64,32,16,8};
__constant__ int c_lOff[4] = {0,34603008,43253760,45416448};
__constant__ int c_lStr[4] = {2883584,720896,180224,45056};   // HW*256 per image

// ---------- pipelined transpose+convert: 64E x 256HW per block ----------
// block boundaries: l0 [0,2112) l1 [2112,2640) l2 [2640,2784) l3 [2784,2832)
__global__ __launch_bounds__(256) void transpose_all_kernel(
    const float* __restrict__ f0, const float* __restrict__ f1,
    const float* __restrict__ f2, const float* __restrict__ f3){
  int bid = blockIdx.x;
  int l, bl;
  if(bid < 2112){ l=0; bl=bid; }
  else if(bid < 2640){ l=1; bl=bid-2112; }
  else if(bid < 2784){ l=2; bl=bid-2640; }
  else { l=3; bl=bid-2784; }
  const float* src; int HW, thw; int dstOff;
  if(l==0){src=f0;HW=11264;thw=44;dstOff=0;}
  else if(l==1){src=f1;HW=2816;thw=11;dstOff=34603008;}
  else if(l==2){src=f2;HW=704;thw=3;dstOff=43253760;}
  else {src=f3;HW=176;thw=1;dstOff=45416448;}
  int e_t = bl & 3; int tmp = bl >> 2;
  int hw_t = tmp % thw; int img = tmp / thw;
  int e0 = e_t*64, hwB = hw_t*256;
  const float* s = src + (size_t)img*E_DIM*HW;
  __half* d = g_fmt + dstOff + (size_t)img*HW*E_DIM;

  __shared__ float sm[64][65];
  int t = threadIdx.x;
  int col = t & 15, row0 = t >> 4;       // load mapping: 16 float4-cols x 16 rows(x4)
  int chunk = t & 7, hrow = t >> 3;      // store mapping: 8 E-chunks x 32 hw-rows(x2)

  float4 regs[4];
  // prologue: load sub-tile 0
  {
    int hwc = hwB + col*4;
    if(hwc < HW){
      #pragma unroll
      for(int i=0;i<4;i++)
        regs[i] = __ldcs((const float4*)(s + (size_t)(e0+row0+16*i)*HW + hwc));
    }
  }

  #pragma unroll
  for(int tt=0; tt<4; tt++){
    int hw0 = hwB + tt*64;
    if(hw0 >= HW) break;
    __syncthreads();                 // prior sub-tile's smem reads complete
    {
      int hwc = hwB + tt*64 + col*4;
      if(hwc < HW){
        #pragma unroll
        for(int i=0;i<4;i++){
          int r = row0 + 16*i;
          sm[r][col*4+0]=regs[i].x; sm[r][col*4+1]=regs[i].y;
          sm[r][col*4+2]=regs[i].z; sm[r][col*4+3]=regs[i].w;
        }
      }
    }
    __syncthreads();                 // smem tile ready
    // issue loads for next sub-tile (in flight during store phase)
    if(tt < 3){
      int hwc = hwB + (tt+1)*64 + col*4;
      if(hwc < HW){
        #pragma unroll
        for(int i=0;i<4;i++)
          regs[i] = __ldcs((const float4*)(s + (size_t)(e0+row0+16*i)*HW + hwc));
      }
    }
    // store phase for sub-tile tt
    #pragma unroll
    for(int i=0;i<2;i++){
      int hw = hrow + 32*i;
      if(hw0+hw < HW){
        __half2 h[4];
        #pragma unroll
        for(int j=0;j<4;j++)
          h[j] = __floats2half2_rn(sm[8*chunk+2*j][hw], sm[8*chunk+2*j+1][hw]);
        *(uint4*)(d + (size_t)(hw0+hw)*E_DIM + e0 + 8*chunk) = *(uint4*)h;
      }
    }
  }
}

// ---------- tiled fp32 GEMM; rows<M1 use A(+A2), rows>=M1 use A3 ----------
__global__ __launch_bounds__(256) void gemm_kernel(
    const float* __restrict__ A, const float* __restrict__ A2,
    const float* __restrict__ A3, int M1,
    const float* __restrict__ B, const float* __restrict__ bias,
    float* __restrict__ C, int M, int N, int ldc){
  __shared__ float As[16][64];
  __shared__ float Bs[16][68];
  int m0 = blockIdx.x*64, n0 = blockIdx.y*64;
  int t = threadIdx.x;
  int tm = t>>4, tn = t&15;
  int rowA = t>>2, kvA = (t&3)<<2;
  int kkB = t>>4, nvB = (t&15)<<2;
  int gm = m0+rowA;
  int gn = n0+nvB;
  float acc[4][4];
  #pragma unroll
  for(int i=0;i<4;i++)
    #pragma unroll
    for(int j=0;j<4;j++) acc[i][j]=0.f;

  const float* Ap = nullptr;
  const float* A2p = nullptr;
  if(gm < M){
    if(A3 && gm >= M1){ Ap = A3 + (size_t)(gm-M1)*E_DIM + kvA; }
    else { Ap = A + (size_t)gm*E_DIM + kvA; if(A2) A2p = A2 + (size_t)gm*E_DIM + kvA; }
  }

  float4 av = make_float4(0,0,0,0), bv = make_float4(0,0,0,0);
  if(Ap){
    av = *(const float4*)(Ap);
    if(A2p){ float4 a2 = *(const float4*)(A2p); av.x+=a2.x; av.y+=a2.y; av.z+=a2.z; av.w+=a2.w; }
  }
  {
    const float* bp = B + (size_t)kkB*N + gn;
    if(gn+3 < N) bv = *(const float4*)bp;
    else { if(gn<N) bv.x=bp[0]; if(gn+1<N) bv.y=bp[1]; if(gn+2<N) bv.z=bp[2]; }
  }

  for(int k0=0; k0<E_DIM; k0+=16){
    __syncthreads();
    As[kvA+0][rowA]=av.x; As[kvA+1][rowA]=av.y;
    As[kvA+2][rowA]=av.z; As[kvA+3][rowA]=av.w;
    *(float4*)&Bs[kkB][nvB] = bv;
    __syncthreads();
    if(k0+16 < E_DIM){
      av = make_float4(0,0,0,0);
      if(Ap){
        av = *(const float4*)(Ap + k0 + 16);
        if(A2p){ float4 a2 = *(const float4*)(A2p + k0 + 16); av.x+=a2.x; av.y+=a2.y; av.z+=a2.z; av.w+=a2.w; }
      }
      const float* bp = B + (size_t)(k0+16+kkB)*N + gn;
      if(gn+3 < N) bv = *(const float4*)bp;
      else { bv=make_float4(0,0,0,0); if(gn<N) bv.x=bp[0]; if(gn+1<N) bv.y=bp[1]; if(gn+2<N) bv.z=bp[2]; }
    }
    #pragma unroll
    for(int kk=0;kk<16;kk++){
      float a[4], b[4];
      *(float4*)a = *(const float4*)&As[kk][tm*4];
      *(float4*)b = *(const float4*)&Bs[kk][tn*4];
      #pragma unroll
      for(int i=0;i<4;i++)
        #pragma unroll
        for(int j=0;j<4;j++)
          acc[i][j] += a[i]*b[j];
    }
  }
  #pragma unroll
  for(int i=0;i<4;i++){
    int gmo = m0 + tm*4 + i;
    if(gmo >= M) continue;
    int gn0 = n0 + tn*4;
    float* cp = C + (size_t)gmo*ldc + gn0;
    #pragma unroll
    for(int j=0;j<4;j++){
      int gno = gn0 + j;
      if(gno < N) cp[j] = acc[i][j] + (bias ? bias[gno] : 0.f);
    }
  }
}

// ---------- learned scales ----------
__global__ __launch_bounds__(256) void ls_kernel(const float* __restrict__ iff,
    const float* __restrict__ lfcw, const float* __restrict__ lfcb){
  int idx = blockIdx.x*256 + threadIdx.x;
  if(idx >= NANCH*18) return;
  int a = idx/18, o = idx - 18*a;
  const float* f = iff + (size_t)a*E_DIM;
  float v = lfcb[o];
  #pragma unroll 4
  for(int e=0;e<E_DIM;e++) v += f[e]*lfcw[e*18+o];
  g_ls[idx] = 1.f/(1.f+__expf(-v)) - 0.5f;
}

// ---------- cam layer1: 12->256 + ReLU + LN ----------
__device__ __forceinline__ float blockSum256(float v, float* red){
  int tid = threadIdx.x;
  red[tid] = v; __syncthreads();
  #pragma unroll
  for(int s=128;s>0;s>>=1){
    if(tid<s) red[tid]+=red[tid+s];
    __syncthreads();
  }
  float r = red[0]; __syncthreads();
  return r;
}

__global__ void cam1_kernel(const float* __restrict__ pm,
    const float* __restrict__ ce1w, const float* __restrict__ ce1b,
    const float* __restrict__ ln1g, const float* __restrict__ ln1b){
  int img = blockIdx.x;
  int tid = threadIdx.x;
  __shared__ float cam[12];
  __shared__ float red[E_DIM];
  if(tid<12) cam[tid] = pm[img*16 + tid];
  __syncthreads();
  float v = ce1b[tid];
  #pragma unroll
  for(int i=0;i<12;i++) v += cam[i]*ce1w[i*E_DIM+tid];
  v = fmaxf(v,0.f);
  float m = blockSum256(v, red) * (1.f/E_DIM);
  float dvar = v - m;
  float var = blockSum256(dvar*dvar, red) * (1.f/E_DIM);
  g_h1[img*E_DIM + tid] = dvar * rsqrtf(var + 1e-5f) * ln1g[tid] + ln1b[tid];
}

// ---------- cam layer2 matmul: grid (12,4); 64 outputs x 4 K-slices ----------
__global__ __launch_bounds__(256) void cam2_kernel(
    const float* __restrict__ ce2w, const float* __restrict__ ce2b){
  int img = blockIdx.x, chunk = blockIdx.y;
  int tid = threadIdx.x;
  int ol = tid & 63, ks = tid >> 6;
  int o = chunk*64 + ol;
  __shared__ float h[E_DIM];
  __shared__ float red[4][64];
  h[tid] = g_h1[img*E_DIM + tid];
  __syncthreads();
  float acc = 0.f;
  int k0 = ks*64;
  #pragma unroll 8
  for(int k=0;k<64;k++)
    acc += h[k0+k]*ce2w[(size_t)(k0+k)*E_DIM + o];
  red[ks][ol] = acc;
  __syncthreads();
  if(ks==0)
    g_ce2[img*E_DIM + o] = red[0][ol]+red[1][ol]+red[2][ol]+red[3][ol] + ce2b[o];
}

// ---------- cam layer2 epilogue: ReLU + LN ----------
__global__ void cam_ln_kernel(const float* __restrict__ ln2g, const float* __restrict__ ln2b){
  int img = blockIdx.x;
  int tid = threadIdx.x;
  __shared__ float red[E_DIM];
  float v = fmaxf(g_ce2[img*E_DIM + tid], 0.f);
  float m = blockSum256(v, red) * (1.f/E_DIM);
  float d = v - m;
  float var = blockSum256(d*d, red) * (1.f/E_DIM);
  g_ce[img*E_DIM + tid] = d * rsqrtf(var + 1e-5f) * ln2g[tid] + ln2b[tid];
}

// ---------- main: 512 threads; atomic-free conflict-free reduction ----------
__global__ __launch_bounds__(512) void dfa_main_kernel(
    const float* __restrict__ iff, const float* __restrict__ anc,
    const float* __restrict__ pm, const float* __restrict__ wh,
    const float* __restrict__ wfb,
    float* __restrict__ out){
  int n = blockIdx.x;
  int b = n / NA;
  int tid = threadIdx.x;
  int wid = tid>>5, ln = tid&31;

  __shared__ float sA[11];
  __shared__ float sLS[18];
  __shared__ float sKP[NPTS][3];
  __shared__ float sWgt[NCAM*WO];
  __shared__ float sGX[NSAMP], sGY[NSAMP];
  __shared__ int   sOff[NSAMP];
  __shared__ int   sWHs[NSAMP];
  __shared__ short sSid[NSAMP];
  __shared__ int   sNV;
  __shared__ float sPart[16][E_DIM];   // per-warp partials, layout [w][j*32+ln]

  // phase A: loads + logits + keypoints
  if(tid < E_DIM)
    out[(size_t)n*512 + 256 + tid] = iff[(size_t)n*E_DIM + tid];
  if(tid==0) sNV = 0;
  if(tid<11) sA[tid] = anc[(size_t)n*11+tid];
  if(tid<18) sLS[tid] = g_ls[n*18+tid];
  // vectorized logit assembly: 2496 floats = 624 float4
  {
    const float4* fA = (const float4*)(g_featW + (size_t)n*WO);
    for(int idx4=tid; idx4<624; idx4+=512){
      int c = idx4/104, o4 = idx4 - c*104;
      float4 a = fA[o4];
      float4 ce = *((const float4*)(g_featW + (size_t)(NANCH + b*NCAM+c)*WO) + o4);
      float4 bb = *((const float4*)wfb + o4);
      float4 r;
      r.x = a.x+ce.x+bb.x; r.y = a.y+ce.y+bb.y;
      r.z = a.z+ce.z+bb.z; r.w = a.w+ce.w+bb.w;
      *(float4*)&sWgt[c*WO + o4*4] = r;
    }
  }
  __syncthreads();
  if(tid<NPTS){
    float sx = expf(sA[3]), sy2 = expf(sA[4]), sz = expf(sA[5]);
    float kx,ky,kz;
    if(tid<7){ kx=c_fix[tid][0]*sx; ky=c_fix[tid][1]*sy2; kz=c_fix[tid][2]*sz; }
    else { int i=tid-7; kx=sLS[i*3+0]*sx; ky=sLS[i*3+1]*sy2; kz=sLS[i*3+2]*sz; }
    float sn = sA[6], cs = sA[7];
    sKP[tid][0] = cs*kx - sn*ky + sA[0];
    sKP[tid][1] = sn*kx + cs*ky + sA[1];
    sKP[tid][2] = kz + sA[2];
  }
  __syncthreads();

  // phase B: warps 0-7 softmax (group = wid); warps 8-15 projection + compaction
  if(wid < 8){
    int g = wid;
    float mx = -1e30f;
    for(int j=ln;j<SOFTN;j+=32){
      int c=j/52, k=j-c*52;
      mx = fmaxf(mx, sWgt[c*WO + k*8 + g]);
    }
    #pragma unroll
    for(int o=16;o;o>>=1) mx = fmaxf(mx, __shfl_xor_sync(0xffffffffu, mx, o));
    float sum = 0.f;
    for(int j=ln;j<SOFTN;j+=32){
      int c=j/52, k=j-c*52;
      sum += __expf(sWgt[c*WO + k*8 + g] - mx);
    }
    #pragma unroll
    for(int o=16;o;o>>=1) sum += __shfl_xor_sync(0xffffffffu, sum, o);
    float inv = 1.f/sum;
    for(int j=ln;j<SOFTN;j+=32){
      int c=j/52, k=j-c*52;
      int idx = c*WO + k*8 + g;
      sWgt[idx] = __expf(sWgt[idx] - mx) * inv;
    }
  } else {
    for(int idx=(wid-8)*32+ln; idx<NSAMP; idx+=256){
      int c = idx/52, r = idx - c*52, l = r/13, p = r - l*13;
      const float* P = pm + (size_t)(b*NCAM+c)*16;
      float X = sKP[p][0], Y = sKP[p][1], Z = sKP[p][2];
      float r0 = P[0]*X + P[1]*Y + P[2]*Z  + P[3];
      float r1 = P[4]*X + P[5]*Y + P[6]*Z  + P[7];
      float r2 = P[8]*X + P[9]*Y + P[10]*Z + P[11];
      float z = fmaxf(r2, 1e-5f);
      float iwx = wh[(b*NCAM+c)*2+0], iwy = wh[(b*NCAM+c)*2+1];
      int Wl = c_lW[l], Hl = c_lH[l];
      float fW = (float)Wl, fH = (float)Hl;
      float gx = (r0/z)/iwx*fW - 0.5f;
      float gy = (r1/z)/iwy*fH - 0.5f;
      sGX[idx] = gx; sGY[idx] = gy;
      sOff[idx] = c_lOff[l] + (b*NCAM+c)*c_lStr[l];
      sWHs[idx] = Wl | (Hl<<16);
      if(gx > -1.f && gx < fW && gy > -1.f && gy < fH){
        int pos = atomicAdd(&sNV, 1);
        sSid[pos] = (short)idx;
      }
    }
  }
  __syncthreads();

  // phase C: sampling with 16 warps; lane owns channels [8*ln..8*ln+7] (group ln>>2)
  float acc[8];
  #pragma unroll
  for(int j=0;j<8;j++) acc[j]=0.f;
  int g = ln>>2;
  int nv = sNV;

  for(int i = wid; i < nv; i += 16){
    int s = sSid[i];
    int whp = sWHs[s];
    int Wl = whp & 0xffff, Hl = whp >> 16;
    float gx = sGX[s], gy = sGY[s];
    float x0f = floorf(gx), y0f = floorf(gy);
    float wx1 = gx - x0f, wy1 = gy - y0f;
    float wx0 = 1.f - wx1, wy0 = 1.f - wy1;
    int x0 = (int)x0f, y0 = (int)y0f;
    bool vx0 = (x0 >= 0), vx1 = (x0+1 < Wl);
    bool vy0 = (y0 >= 0), vy1 = (y0+1 < Hl);
    const __half* imgb = g_fmt + sOff[s];
    float sv[8];
    #pragma unroll
    for(int j=0;j<8;j++) sv[j]=0.f;
    #define TAP(px, py, wt) { \
      uint4 u = *((const uint4*)(imgb + ((size_t)((py)*Wl + (px))<<8)) + ln); \
      const __half2* hp = (const __half2*)&u; \
      _Pragma("unroll") \
      for(int j=0;j<4;j++){ \
        float2 f = __half22float2(hp[j]); \
        sv[2*j]   += (wt)*f.x; \
        sv[2*j+1] += (wt)*f.y; \
      } }
    if(vy0){
      if(vx0) TAP(x0,   y0, wx0*wy0);
      if(vx1) TAP(x0+1, y0, wx1*wy0);
    }
    if(vy1){
      if(vx0) TAP(x0,   y0+1, wx0*wy1);
      if(vx1) TAP(x0+1, y0+1, wx1*wy1);
    }
    #undef TAP
    float wt = sWgt[s*8 + g];
    #pragma unroll
    for(int j=0;j<8;j++) acc[j] += wt*sv[j];
  }
  // conflict-free partial stores: position j*32+ln holds channel 8*ln+j
  #pragma unroll
  for(int j=0;j<8;j++) sPart[wid][j*32+ln] = acc[j];
  __syncthreads();
  if(tid < E_DIM){
    int pos = (tid&7)*32 + (tid>>3);
    float s = 0.f;
    #pragma unroll
    for(int w=0;w<16;w++) s += sPart[w][pos];
    g_fused[(size_t)n*E_DIM + tid] = s;
  }
}

// ---------- host launcher ----------
extern "C" void kernel_launch(void* const* d_in, const int* in_sizes, int n_in,
                              void* d_out, int out_size) {
  int iIF=0, iAE=2, iPM, iWH, iFM0, iFM1, iFM2, iFM3;
  int iANC=1;
  if(in_sizes[3]==192){ iPM=3; iWH=4; iFM0=5; iFM1=6; iFM2=7; iFM3=8; }
  else                { iFM0=3; iFM1=4; iFM2=5; iFM3=6; iPM=7; iWH=8; }
  int iLFW=9, iLFB=10, iC1W=11, iC1B=12, iL1G=13, iL1B=14,
      iC2W=15, iC2B=16, iL2G=17, iL2B=18, iWFW=19, iWFB=20, iOPW=21, iOPB=22;

  const float* iff  = (const float*)d_in[iIF];
  const float* anc  = (const float*)d_in[iANC];
  const float* ae   = (const float*)d_in[iAE];
  const float* pm   = (const float*)d_in[iPM];
  const float* wh   = (const float*)d_in[iWH];
  const float* fm0  = (const float*)d_in[iFM0];
  const float* fm1  = (const float*)d_in[iFM1];
  const float* fm2  = (const float*)d_in[iFM2];
  const float* fm3  = (const float*)d_in[iFM3];
  const float* lfcw = (const float*)d_in[iLFW];
  const float* lfcb = (const float*)d_in[iLFB];
  const float* c1w  = (const float*)d_in[iC1W];
  const float* c1b  = (const float*)d_in[iC1B];
  const float* l1g  = (const float*)d_in[iL1G];
  const float* l1b  = (const float*)d_in[iL1B];
  const float* c2w  = (const float*)d_in[iC2W];
  const float* c2b  = (const float*)d_in[iC2B];
  const float* l2g  = (const float*)d_in[iL2G];
  const float* l2b  = (const float*)d_in[iL2B];
  const float* wfw  = (const float*)d_in[iWFW];
  const float* wfb  = (const float*)d_in[iWFB];
  const float* opw  = (const float*)d_in[iOPW];
  const float* opb  = (const float*)d_in[iOPB];
  float* out = (float*)d_out;

  float* p_featW; cudaGetSymbolAddress((void**)&p_featW, g_featW);
  float* p_fused; cudaGetSymbolAddress((void**)&p_fused, g_fused);
  float* p_ce;    cudaGetSymbolAddress((void**)&p_ce,    g_ce);

  static cudaStream_t s2 = nullptr;
  static cudaEvent_t evFork=nullptr, evJoin=nullptr;
  if(s2 == nullptr){
    cudaStreamCreateWithFlags(&s2, cudaStreamNonBlocking);
    cudaEventCreateWithFlags(&evFork, cudaEventDisableTiming);
    cudaEventCreateWithFlags(&evJoin, cudaEventDisableTiming);
  }

  // fork
  cudaEventRecord(evFork, 0);
  cudaStreamWaitEvent(s2, evFork, 0);

  // stream 0: pipelined merged transpose (full chip)
  transpose_all_kernel<<<2832, 256>>>(fm0, fm1, fm2, fm3);

  // stream 2: weight-side pipeline (independent of g_fmt)
  ls_kernel<<<(NANCH*18 + 255)/256, 256, 0, s2>>>(iff, lfcw, lfcb);
  cam1_kernel<<<12, 256, 0, s2>>>(pm, c1w, c1b, l1g, l1b);
  cam2_kernel<<<dim3(12,4), 256, 0, s2>>>(c2w, c2b);
  cam_ln_kernel<<<12, 256, 0, s2>>>(l2g, l2b);
  // combined GEMM: rows 0..1799 = (iff+ae)@wfw ; rows 1800..1811 = ce@wfw (no bias)
  gemm_kernel<<<dim3(29,7), 256, 0, s2>>>(iff, ae, p_ce, NANCH, wfw, nullptr,
                                          p_featW, MTOT, WO, WO);

  // join
  cudaEventRecord(evJoin, s2);
  cudaStreamWaitEvent(0, evJoin, 0);

  dfa_main_kernel<<<NANCH, 512>>>(iff, anc, pm, wh, wfb, out);
  gemm_kernel<<<dim3(29,4), 256>>>(p_fused, nullptr, nullptr, NANCH, opw, opb,
                                   out, NANCH, E_DIM, 512);
}

// round 16
// speedup vs baseline: 1.1172x; 1.1152x over previous
#include <cuda_runtime.h>
#include <cuda_fp16.h>
#include <cuda_fp8.h>
#include <math.h>
#include <stdint.h>

// Problem constants
#define E_DIM   256
#define NA      900
#define BS      2
#define NCAM    6
#define NLVL    4
#define NPTS    13
#define NG      8
#define NANCH   (BS*NA)          // 1800
#define WO      416              // G*NL*NPTS
#define NSAMP   (NCAM*NLVL*NPTS) // 312
#define SOFTN   312
#define MTOT    (NANCH+12)       // 1812 rows in combined GEMM

// Levels: 0: 64x176  1: 32x88  2: 16x44  3: 8x22
#define FMT_TOTAL 45957120

__device__ unsigned char g_fmt[FMT_TOTAL];   // fp8 e4m3 feature maps
__device__ float  g_featW[MTOT*WO];   // rows 0..1799: featW; rows 1800..1811: ceW (no bias)
__device__ float  g_h1[12*E_DIM];
__device__ float  g_ce2[12*E_DIM];
__device__ float  g_ce[12*E_DIM];
__device__ float  g_ls[NANCH*18];
__device__ float  g_fused[NANCH*E_DIM];

__constant__ float c_fix[7][3] = {
  {0.f,0.f,0.f},{0.45f,0.f,0.f},{-0.45f,0.f,0.f},{0.f,0.45f,0.f},
  {0.f,-0.45f,0.f},{0.f,0.f,0.45f},{0.f,0.f,-0.45f}};

__constant__ int c_lW[4]   = {176,88,44,22};
__constant__ int c_lH[4]   = {64,32,16,8};
__constant__ int c_lOff[4] = {0,34603008,43253760,45416448};
__constant__ int c_lStr[4] = {2883584,720896,180224,45056};   // HW*256 per image (fp8 bytes)

// ---------- pipelined transpose+convert: 64E x 256HW per block, fp8 output ----------
// block boundaries: l0 [0,2112) l1 [2112,2640) l2 [2640,2784) l3 [2784,2832)
__global__ __launch_bounds__(256) void transpose_all_kernel(
    const float* __restrict__ f0, const float* __restrict__ f1,
    const float* __restrict__ f2, const float* __restrict__ f3){
  int bid = blockIdx.x;
  int l, bl;
  if(bid < 2112){ l=0; bl=bid; }
  else if(bid < 2640){ l=1; bl=bid-2112; }
  else if(bid < 2784){ l=2; bl=bid-2640; }
  else { l=3; bl=bid-2784; }
  const float* src; int HW, thw; int dstOff;
  if(l==0){src=f0;HW=11264;thw=44;dstOff=0;}
  else if(l==1){src=f1;HW=2816;thw=11;dstOff=34603008;}
  else if(l==2){src=f2;HW=704;thw=3;dstOff=43253760;}
  else {src=f3;HW=176;thw=1;dstOff=45416448;}
  int e_t = bl & 3; int tmp = bl >> 2;
  int hw_t = tmp % thw; int img = tmp / thw;
  int e0 = e_t*64, hwB = hw_t*256;
  const float* s = src + (size_t)img*E_DIM*HW;
  unsigned char* d = g_fmt + dstOff + (size_t)img*HW*E_DIM;

  __shared__ float sm[64][65];
  int t = threadIdx.x;
  int col = t & 15, row0 = t >> 4;       // load mapping: 16 float4-cols x 16 rows(x4)
  int chunk = t & 7, hrow = t >> 3;      // store mapping: 8 E-chunks x 32 hw-rows(x2)

  float4 regs[4];
  // prologue: load sub-tile 0
  {
    int hwc = hwB + col*4;
    if(hwc < HW){
      #pragma unroll
      for(int i=0;i<4;i++)
        regs[i] = __ldcs((const float4*)(s + (size_t)(e0+row0+16*i)*HW + hwc));
    }
  }

  #pragma unroll
  for(int tt=0; tt<4; tt++){
    int hw0 = hwB + tt*64;
    if(hw0 >= HW) break;
    __syncthreads();
    {
      int hwc = hwB + tt*64 + col*4;
      if(hwc < HW){
        #pragma unroll
        for(int i=0;i<4;i++){
          int r = row0 + 16*i;
          sm[r][col*4+0]=regs[i].x; sm[r][col*4+1]=regs[i].y;
          sm[r][col*4+2]=regs[i].z; sm[r][col*4+3]=regs[i].w;
        }
      }
    }
    __syncthreads();
    if(tt < 3){
      int hwc = hwB + (tt+1)*64 + col*4;
      if(hwc < HW){
        #pragma unroll
        for(int i=0;i<4;i++)
          regs[i] = __ldcs((const float4*)(s + (size_t)(e0+row0+16*i)*HW + hwc));
      }
    }
    // store phase: 8 E values -> 8 fp8 bytes per thread per hw row
    #pragma unroll
    for(int i=0;i<2;i++){
      int hw = hrow + 32*i;
      if(hw0+hw < HW){
        unsigned int p01, p23;
        {
          __nv_fp8x2_storage_t q0 = __nv_cvt_float2_to_fp8x2(
              make_float2(sm[8*chunk+0][hw], sm[8*chunk+1][hw]), __NV_SATFINITE, __NV_E4M3);
          __nv_fp8x2_storage_t q1 = __nv_cvt_float2_to_fp8x2(
              make_float2(sm[8*chunk+2][hw], sm[8*chunk+3][hw]), __NV_SATFINITE, __NV_E4M3);
          __nv_fp8x2_storage_t q2 = __nv_cvt_float2_to_fp8x2(
              make_float2(sm[8*chunk+4][hw], sm[8*chunk+5][hw]), __NV_SATFINITE, __NV_E4M3);
          __nv_fp8x2_storage_t q3 = __nv_cvt_float2_to_fp8x2(
              make_float2(sm[8*chunk+6][hw], sm[8*chunk+7][hw]), __NV_SATFINITE, __NV_E4M3);
          p01 = (unsigned int)q0 | ((unsigned int)q1 << 16);
          p23 = (unsigned int)q2 | ((unsigned int)q3 << 16);
        }
        uint2 u; u.x = p01; u.y = p23;
        *(uint2*)(d + (size_t)(hw0+hw)*E_DIM + e0 + 8*chunk) = u;
      }
    }
  }
}

// ---------- tiled fp32 GEMM; rows<M1 use A(+A2), rows>=M1 use A3 ----------
__global__ __launch_bounds__(256) void gemm_kernel(
    const float* __restrict__ A, const float* __restrict__ A2,
    const float* __restrict__ A3, int M1,
    const float* __restrict__ B, const float* __restrict__ bias,
    float* __restrict__ C, int M, int N, int ldc){
  __shared__ float As[16][64];
  __shared__ float Bs[16][68];
  int m0 = blockIdx.x*64, n0 = blockIdx.y*64;
  int t = threadIdx.x;
  int tm = t>>4, tn = t&15;
  int rowA = t>>2, kvA = (t&3)<<2;
  int kkB = t>>4, nvB = (t&15)<<2;
  int gm = m0+rowA;
  int gn = n0+nvB;
  float acc[4][4];
  #pragma unroll
  for(int i=0;i<4;i++)
    #pragma unroll
    for(int j=0;j<4;j++) acc[i][j]=0.f;

  const float* Ap = nullptr;
  const float* A2p = nullptr;
  if(gm < M){
    if(A3 && gm >= M1){ Ap = A3 + (size_t)(gm-M1)*E_DIM + kvA; }
    else { Ap = A + (size_t)gm*E_DIM + kvA; if(A2) A2p = A2 + (size_t)gm*E_DIM + kvA; }
  }

  float4 av = make_float4(0,0,0,0), bv = make_float4(0,0,0,0);
  if(Ap){
    av = *(const float4*)(Ap);
    if(A2p){ float4 a2 = *(const float4*)(A2p); av.x+=a2.x; av.y+=a2.y; av.z+=a2.z; av.w+=a2.w; }
  }
  {
    const float* bp = B + (size_t)kkB*N + gn;
    if(gn+3 < N) bv = *(const float4*)bp;
    else { if(gn<N) bv.x=bp[0]; if(gn+1<N) bv.y=bp[1]; if(gn+2<N) bv.z=bp[2]; }
  }

  for(int k0=0; k0<E_DIM; k0+=16){
    __syncthreads();
    As[kvA+0][rowA]=av.x; As[kvA+1][rowA]=av.y;
    As[kvA+2][rowA]=av.z; As[kvA+3][rowA]=av.w;
    *(float4*)&Bs[kkB][nvB] = bv;
    __syncthreads();
    if(k0+16 < E_DIM){
      av = make_float4(0,0,0,0);
      if(Ap){
        av = *(const float4*)(Ap + k0 + 16);
        if(A2p){ float4 a2 = *(const float4*)(A2p + k0 + 16); av.x+=a2.x; av.y+=a2.y; av.z+=a2.z; av.w+=a2.w; }
      }
      const float* bp = B + (size_t)(k0+16+kkB)*N + gn;
      if(gn+3 < N) bv = *(const float4*)bp;
      else { bv=make_float4(0,0,0,0); if(gn<N) bv.x=bp[0]; if(gn+1<N) bv.y=bp[1]; if(gn+2<N) bv.z=bp[2]; }
    }
    #pragma unroll
    for(int kk=0;kk<16;kk++){
      float a[4], b[4];
      *(float4*)a = *(const float4*)&As[kk][tm*4];
      *(float4*)b = *(const float4*)&Bs[kk][tn*4];
      #pragma unroll
      for(int i=0;i<4;i++)
        #pragma unroll
        for(int j=0;j<4;j++)
          acc[i][j] += a[i]*b[j];
    }
  }
  #pragma unroll
  for(int i=0;i<4;i++){
    int gmo = m0 + tm*4 + i;
    if(gmo >= M) continue;
    int gn0 = n0 + tn*4;
    float* cp = C + (size_t)gmo*ldc + gn0;
    #pragma unroll
    for(int j=0;j<4;j++){
      int gno = gn0 + j;
      if(gno < N) cp[j] = acc[i][j] + (bias ? bias[gno] : 0.f);
    }
  }
}

// ---------- learned scales ----------
__global__ __launch_bounds__(256) void ls_kernel(const float* __restrict__ iff,
    const float* __restrict__ lfcw, const float* __restrict__ lfcb){
  int idx = blockIdx.x*256 + threadIdx.x;
  if(idx >= NANCH*18) return;
  int a = idx/18, o = idx - 18*a;
  const float* f = iff + (size_t)a*E_DIM;
  float v = lfcb[o];
  #pragma unroll 4
  for(int e=0;e<E_DIM;e++) v += f[e]*lfcw[e*18+o];
  g_ls[idx] = 1.f/(1.f+__expf(-v)) - 0.5f;
}

// ---------- cam layer1: 12->256 + ReLU + LN ----------
__device__ __forceinline__ float blockSum256(float v, float* red){
  int tid = threadIdx.x;
  red[tid] = v; __syncthreads();
  #pragma unroll
  for(int s=128;s>0;s>>=1){
    if(tid<s) red[tid]+=red[tid+s];
    __syncthreads();
  }
  float r = red[0]; __syncthreads();
  return r;
}

__global__ void cam1_kernel(const float* __restrict__ pm,
    const float* __restrict__ ce1w, const float* __restrict__ ce1b,
    const float* __restrict__ ln1g, const float* __restrict__ ln1b){
  int img = blockIdx.x;
  int tid = threadIdx.x;
  __shared__ float cam[12];
  __shared__ float red[E_DIM];
  if(tid<12) cam[tid] = pm[img*16 + tid];
  __syncthreads();
  float v = ce1b[tid];
  #pragma unroll
  for(int i=0;i<12;i++) v += cam[i]*ce1w[i*E_DIM+tid];
  v = fmaxf(v,0.f);
  float m = blockSum256(v, red) * (1.f/E_DIM);
  float dvar = v - m;
  float var = blockSum256(dvar*dvar, red) * (1.f/E_DIM);
  g_h1[img*E_DIM + tid] = dvar * rsqrtf(var + 1e-5f) * ln1g[tid] + ln1b[tid];
}

// ---------- cam layer2 matmul: grid (12,4); 64 outputs x 4 K-slices ----------
__global__ __launch_bounds__(256) void cam2_kernel(
    const float* __restrict__ ce2w, const float* __restrict__ ce2b){
  int img = blockIdx.x, chunk = blockIdx.y;
  int tid = threadIdx.x;
  int ol = tid & 63, ks = tid >> 6;
  int o = chunk*64 + ol;
  __shared__ float h[E_DIM];
  __shared__ float red[4][64];
  h[tid] = g_h1[img*E_DIM + tid];
  __syncthreads();
  float acc = 0.f;
  int k0 = ks*64;
  #pragma unroll 8
  for(int k=0;k<64;k++)
    acc += h[k0+k]*ce2w[(size_t)(k0+k)*E_DIM + o];
  red[ks][ol] = acc;
  __syncthreads();
  if(ks==0)
    g_ce2[img*E_DIM + o] = red[0][ol]+red[1][ol]+red[2][ol]+red[3][ol] + ce2b[o];
}

// ---------- cam layer2 epilogue: ReLU + LN ----------
__global__ void cam_ln_kernel(const float* __restrict__ ln2g, const float* __restrict__ ln2b){
  int img = blockIdx.x;
  int tid = threadIdx.x;
  __shared__ float red[E_DIM];
  float v = fmaxf(g_ce2[img*E_DIM + tid], 0.f);
  float m = blockSum256(v, red) * (1.f/E_DIM);
  float d = v - m;
  float var = blockSum256(d*d, red) * (1.f/E_DIM);
  g_ce[img*E_DIM + tid] = d * rsqrtf(var + 1e-5f) * ln2g[tid] + ln2b[tid];
}

// ---------- main: 512 threads; fp8 gather; atomic-free reduction ----------
__global__ __launch_bounds__(512) void dfa_main_kernel(
    const float* __restrict__ iff, const float* __restrict__ anc,
    const float* __restrict__ pm, const float* __restrict__ wh,
    const float* __restrict__ wfb,
    float* __restrict__ out){
  int n = blockIdx.x;
  int b = n / NA;
  int tid = threadIdx.x;
  int wid = tid>>5, ln = tid&31;

  __shared__ float sA[11];
  __shared__ float sLS[18];
  __shared__ float sKP[NPTS][3];
  __shared__ float sWgt[NCAM*WO];
  __shared__ float sGX[NSAMP], sGY[NSAMP];
  __shared__ int   sOff[NSAMP];
  __shared__ int   sWHs[NSAMP];
  __shared__ short sSid[NSAMP];
  __shared__ int   sNV;
  __shared__ float sPart[16][E_DIM];   // per-warp partials, layout [w][j*32+ln]

  // phase A: loads + logits + keypoints
  if(tid < E_DIM)
    out[(size_t)n*512 + 256 + tid] = iff[(size_t)n*E_DIM + tid];
  if(tid==0) sNV = 0;
  if(tid<11) sA[tid] = anc[(size_t)n*11+tid];
  if(tid<18) sLS[tid] = g_ls[n*18+tid];
  // vectorized logit assembly: 2496 floats = 624 float4
  {
    const float4* fA = (const float4*)(g_featW + (size_t)n*WO);
    for(int idx4=tid; idx4<624; idx4+=512){
      int c = idx4/104, o4 = idx4 - c*104;
      float4 a = fA[o4];
      float4 ce = *((const float4*)(g_featW + (size_t)(NANCH + b*NCAM+c)*WO) + o4);
      float4 bb = *((const float4*)wfb + o4);
      float4 r;
      r.x = a.x+ce.x+bb.x; r.y = a.y+ce.y+bb.y;
      r.z = a.z+ce.z+bb.z; r.w = a.w+ce.w+bb.w;
      *(float4*)&sWgt[c*WO + o4*4] = r;
    }
  }
  __syncthreads();
  if(tid<NPTS){
    float sx = expf(sA[3]), sy2 = expf(sA[4]), sz = expf(sA[5]);
    float kx,ky,kz;
    if(tid<7){ kx=c_fix[tid][0]*sx; ky=c_fix[tid][1]*sy2; kz=c_fix[tid][2]*sz; }
    else { int i=tid-7; kx=sLS[i*3+0]*sx; ky=sLS[i*3+1]*sy2; kz=sLS[i*3+2]*sz; }
    float sn = sA[6], cs = sA[7];
    sKP[tid][0] = cs*kx - sn*ky + sA[0];
    sKP[tid][1] = sn*kx + cs*ky + sA[1];
    sKP[tid][2] = kz + sA[2];
  }
  __syncthreads();

  // phase B: warps 0-7 softmax (group = wid); warps 8-15 projection + compaction
  if(wid < 8){
    int g = wid;
    float mx = -1e30f;
    for(int j=ln;j<SOFTN;j+=32){
      int c=j/52, k=j-c*52;
      mx = fmaxf(mx, sWgt[c*WO + k*8 + g]);
    }
    #pragma unroll
    for(int o=16;o;o>>=1) mx = fmaxf(mx, __shfl_xor_sync(0xffffffffu, mx, o));
    float sum = 0.f;
    for(int j=ln;j<SOFTN;j+=32){
      int c=j/52, k=j-c*52;
      sum += __expf(sWgt[c*WO + k*8 + g] - mx);
    }
    #pragma unroll
    for(int o=16;o;o>>=1) sum += __shfl_xor_sync(0xffffffffu, sum, o);
    float inv = 1.f/sum;
    for(int j=ln;j<SOFTN;j+=32){
      int c=j/52, k=j-c*52;
      int idx = c*WO + k*8 + g;
      sWgt[idx] = __expf(sWgt[idx] - mx) * inv;
    }
  } else {
    for(int idx=(wid-8)*32+ln; idx<NSAMP; idx+=256){
      int c = idx/52, r = idx - c*52, l = r/13, p = r - l*13;
      const float* P = pm + (size_t)(b*NCAM+c)*16;
      float X = sKP[p][0], Y = sKP[p][1], Z = sKP[p][2];
      float r0 = P[0]*X + P[1]*Y + P[2]*Z  + P[3];
      float r1 = P[4]*X + P[5]*Y + P[6]*Z  + P[7];
      float r2 = P[8]*X + P[9]*Y + P[10]*Z + P[11];
      float z = fmaxf(r2, 1e-5f);
      float iwx = wh[(b*NCAM+c)*2+0], iwy = wh[(b*NCAM+c)*2+1];
      int Wl = c_lW[l], Hl = c_lH[l];
      float fW = (float)Wl, fH = (float)Hl;
      float gx = (r0/z)/iwx*fW - 0.5f;
      float gy = (r1/z)/iwy*fH - 0.5f;
      sGX[idx] = gx; sGY[idx] = gy;
      sOff[idx] = c_lOff[l] + (b*NCAM+c)*c_lStr[l];
      sWHs[idx] = Wl | (Hl<<16);
      if(gx > -1.f && gx < fW && gy > -1.f && gy < fH){
        int pos = atomicAdd(&sNV, 1);
        sSid[pos] = (short)idx;
      }
    }
  }
  __syncthreads();

  // phase C: sampling with 16 warps; lane owns channels [8*ln..8*ln+7] (group ln>>2)
  float acc[8];
  #pragma unroll
  for(int j=0;j<8;j++) acc[j]=0.f;
  int g = ln>>2;
  int nv = sNV;

  for(int i = wid; i < nv; i += 16){
    int s = sSid[i];
    int whp = sWHs[s];
    int Wl = whp & 0xffff, Hl = whp >> 16;
    float gx = sGX[s], gy = sGY[s];
    float x0f = floorf(gx), y0f = floorf(gy);
    float wx1 = gx - x0f, wy1 = gy - y0f;
    float wx0 = 1.f - wx1, wy0 = 1.f - wy1;
    int x0 = (int)x0f, y0 = (int)y0f;
    bool vx0 = (x0 >= 0), vx1 = (x0+1 < Wl);
    bool vy0 = (y0 >= 0), vy1 = (y0+1 < Hl);
    const unsigned char* imgb = g_fmt + sOff[s];
    float sv[8];
    #pragma unroll
    for(int j=0;j<8;j++) sv[j]=0.f;
    #define TAP(px, py, wt) { \
      uint2 u = *((const uint2*)(imgb + ((size_t)((py)*Wl + (px))<<8)) + ln); \
      unsigned short q0 = (unsigned short)(u.x & 0xffff); \
      unsigned short q1 = (unsigned short)(u.x >> 16); \
      unsigned short q2 = (unsigned short)(u.y & 0xffff); \
      unsigned short q3 = (unsigned short)(u.y >> 16); \
      __half2_raw h0 = __nv_cvt_fp8x2_to_halfraw2(q0, __NV_E4M3); \
      __half2_raw h1 = __nv_cvt_fp8x2_to_halfraw2(q1, __NV_E4M3); \
      __half2_raw h2 = __nv_cvt_fp8x2_to_halfraw2(q2, __NV_E4M3); \
      __half2_raw h3 = __nv_cvt_fp8x2_to_halfraw2(q3, __NV_E4M3); \
      float2 f0 = __half22float2(*(__half2*)&h0); \
      float2 f1 = __half22float2(*(__half2*)&h1); \
      float2 f2 = __half22float2(*(__half2*)&h2); \
      float2 f3 = __half22float2(*(__half2*)&h3); \
      sv[0] += (wt)*f0.x; sv[1] += (wt)*f0.y; \
      sv[2] += (wt)*f1.x; sv[3] += (wt)*f1.y; \
      sv[4] += (wt)*f2.x; sv[5] += (wt)*f2.y; \
      sv[6] += (wt)*f3.x; sv[7] += (wt)*f3.y; }
    if(vy0){
      if(vx0) TAP(x0,   y0, wx0*wy0);
      if(vx1) TAP(x0+1, y0, wx1*wy0);
    }
    if(vy1){
      if(vx0) TAP(x0,   y0+1, wx0*wy1);
      if(vx1) TAP(x0+1, y0+1, wx1*wy1);
    }
    #undef TAP
    float wt = sWgt[s*8 + g];
    #pragma unroll
    for(int j=0;j<8;j++) acc[j] += wt*sv[j];
  }
  // conflict-free partial stores: position j*32+ln holds channel 8*ln+j
  #pragma unroll
  for(int j=0;j<8;j++) sPart[wid][j*32+ln] = acc[j];
  __syncthreads();
  if(tid < E_DIM){
    int pos = (tid&7)*32 + (tid>>3);
    float s = 0.f;
    #pragma unroll
    for(int w=0;w<16;w++) s += sPart[w][pos];
    g_fused[(size_t)n*E_DIM + tid] = s;
  }
}

// ---------- host launcher ----------
extern "C" void kernel_launch(void* const* d_in, const int* in_sizes, int n_in,
                              void* d_out, int out_size) {
  int iIF=0, iAE=2, iPM, iWH, iFM0, iFM1, iFM2, iFM3;
  int iANC=1;
  if(in_sizes[3]==192){ iPM=3; iWH=4; iFM0=5; iFM1=6; iFM2=7; iFM3=8; }
  else                { iFM0=3; iFM1=4; iFM2=5; iFM3=6; iPM=7; iWH=8; }
  int iLFW=9, iLFB=10, iC1W=11, iC1B=12, iL1G=13, iL1B=14,
      iC2W=15, iC2B=16, iL2G=17, iL2B=18, iWFW=19, iWFB=20, iOPW=21, iOPB=22;

  const float* iff  = (const float*)d_in[iIF];
  const float* anc  = (const float*)d_in[iANC];
  const float* ae   = (const float*)d_in[iAE];
  const float* pm   = (const float*)d_in[iPM];
  const float* wh   = (const float*)d_in[iWH];
  const float* fm0  = (const float*)d_in[iFM0];
  const float* fm1  = (const float*)d_in[iFM1];
  const float* fm2  = (const float*)d_in[iFM2];
  const float* fm3  = (const float*)d_in[iFM3];
  const float* lfcw = (const float*)d_in[iLFW];
  const float* lfcb = (const float*)d_in[iLFB];
  const float* c1w  = (const float*)d_in[iC1W];
  const float* c1b  = (const float*)d_in[iC1B];
  const float* l1g  = (const float*)d_in[iL1G];
  const float* l1b  = (const float*)d_in[iL1B];
  const float* c2w  = (const float*)d_in[iC2W];
  const float* c2b  = (const float*)d_in[iC2B];
  const float* l2g  = (const float*)d_in[iL2G];
  const float* l2b  = (const float*)d_in[iL2B];
  const float* wfw  = (const float*)d_in[iWFW];
  const float* wfb  = (const float*)d_in[iWFB];
  const float* opw  = (const float*)d_in[iOPW];
  const float* opb  = (const float*)d_in[iOPB];
  float* out = (float*)d_out;

  float* p_featW; cudaGetSymbolAddress((void**)&p_featW, g_featW);
  float* p_fused; cudaGetSymbolAddress((void**)&p_fused, g_fused);
  float* p_ce;    cudaGetSymbolAddress((void**)&p_ce,    g_ce);

  static cudaStream_t s2 = nullptr;
  static cudaEvent_t evFork=nullptr, evJoin=nullptr;
  if(s2 == nullptr){
    cudaStreamCreateWithFlags(&s2, cudaStreamNonBlocking);
    cudaEventCreateWithFlags(&evFork, cudaEventDisableTiming);
    cudaEventCreateWithFlags(&evJoin, cudaEventDisableTiming);
  }

  // fork
  cudaEventRecord(evFork, 0);
  cudaStreamWaitEvent(s2, evFork, 0);

  // stream 0: pipelined merged transpose (full chip)
  transpose_all_kernel<<<2832, 256>>>(fm0, fm1, fm2, fm3);

  // stream 2: weight-side pipeline (independent of g_fmt)
  ls_kernel<<<(NANCH*18 + 255)/256, 256, 0, s2>>>(iff, lfcw, lfcb);
  cam1_kernel<<<12, 256, 0, s2>>>(pm, c1w, c1b, l1g, l1b);
  cam2_kernel<<<dim3(12,4), 256, 0, s2>>>(c2w, c2b);
  cam_ln_kernel<<<12, 256, 0, s2>>>(l2g, l2b);
  // combined GEMM: rows 0..1799 = (iff+ae)@wfw ; rows 1800..1811 = ce@wfw (no bias)
  gemm_kernel<<<dim3(29,7), 256, 0, s2>>>(iff, ae, p_ce, NANCH, wfw, nullptr,
                                          p_featW, MTOT, WO, WO);

  // join
  cudaEventRecord(evJoin, s2);
  cudaStreamWaitEvent(0, evJoin, 0);

  dfa_main_kernel<<<NANCH, 512>>>(iff, anc, pm, wh, wfb, out);
  gemm_kernel<<<dim3(29,4), 256>>>(p_fused, nullptr, nullptr, NANCH, opw, opb,
                                   out, NANCH, E_DIM, 512);
}